// round 1
// baseline (speedup 1.0000x reference)
#include <cuda_runtime.h>
#include <math.h>

#define N 8192
#define D 1024

// Scratch (allocation-free rule: __device__ globals)
__device__ float g_a[N];      // sigmoid(x @ w)
__device__ float g_b[N];      // cumsum(a), replicating jax associative_scan fp32 rounding
__device__ float g_m[N];      // main weight written at row idx
__device__ float g_c[N];      // cross weight written at row idx-1 (when bin changed)
__device__ int   g_row0[N];   // idx
__device__ int   g_row1[N];   // idx-1 or -1

// ---------------------------------------------------------------------------
// Kernel 1: z = x @ w, a = sigmoid(z).  One warp per row; coalesced float4.
// ---------------------------------------------------------------------------
__global__ void k_logits(const float* __restrict__ x, const float* __restrict__ w) {
    const int warp = threadIdx.x >> 5;
    const int lane = threadIdx.x & 31;
    const int row  = blockIdx.x * 8 + warp;

    const float4* xr = reinterpret_cast<const float4*>(x) + row * (D / 4);
    const float4* w4 = reinterpret_cast<const float4*>(w);

    float s = 0.f;
#pragma unroll
    for (int k = 0; k < D / 128; k++) {           // 8 iterations
        float4 xv = xr[lane + 32 * k];
        float4 wv = __ldg(&w4[lane + 32 * k]);
        s += xv.x * wv.x;
        s += xv.y * wv.y;
        s += xv.z * wv.z;
        s += xv.w * wv.w;
    }
#pragma unroll
    for (int off = 16; off; off >>= 1)
        s += __shfl_xor_sync(0xffffffffu, s, off);

    if (lane == 0) {
        float z = s, a;
        if (z >= 0.f) {
            a = 1.f / (1.f + expf(-z));
        } else {
            float e = expf(z);
            a = e / (1.f + e);
        }
        g_a[row] = a;
    }
}

// ---------------------------------------------------------------------------
// Kernel 2: b = cumsum(a) replicating jax.lax.associative_scan's fp32 rounding
// tree exactly, then derive per-column weights.
//
// associative_scan (n = 2^13):
//   up:   s_l[i] = s_{l-1}[2i] + s_{l-1}[2i+1]
//   down: scan_l[2i+1] = scan_{l+1}[i]
//         scan_l[0]    = s_l[0]
//         scan_l[2i]   = scan_{l+1}[i-1] + s_l[2i]   (i >= 1)
// Levels 1..13 live in shared (8191 floats); level 0 lives in g_a/g_b.
// Down-sweep runs in place (each slot read+written only by its own thread).
// ---------------------------------------------------------------------------
__global__ void k_scan() {
    __shared__ float sh[8192];
    const int tid = threadIdx.x;   // 1024 threads
    // off(l) = 8192 - 2*(8192 >> l) for l in 1..13

    // up-sweep: level 1 from global a
    for (int i = tid; i < 4096; i += 1024)
        sh[i] = g_a[2 * i] + g_a[2 * i + 1];
    __syncthreads();
    // levels 2..13
    for (int l = 2; l <= 13; l++) {
        const int n    = N >> l;
        const int off  = 8192 - 2 * (8192 >> l);
        const int offp = 8192 - 2 * (8192 >> (l - 1));
        for (int i = tid; i < n; i += 1024)
            sh[off + i] = sh[offp + 2 * i] + sh[offp + 2 * i + 1];
        __syncthreads();
    }

    // down-sweep: level 13 is already its own scan (1 element). Do 12..1.
    for (int l = 12; l >= 1; l--) {
        const int n    = N >> l;
        const int off  = 8192 - 2 * (8192 >> l);
        const int offc = 8192 - 2 * (8192 >> (l + 1));
        for (int i = tid; i < n; i += 1024) {
            float v;
            if (i & 1)       v = sh[offc + (i >> 1)];
            else if (i == 0) v = sh[off];
            else             v = sh[offc + (i >> 1) - 1] + sh[off + i];
            sh[off + i] = v;
        }
        __syncthreads();
    }

    // level 0 -> g_b
    for (int i = tid; i < N; i += 1024) {
        float v;
        if (i == 0)      v = g_a[0];
        else if (i & 1)  v = sh[i >> 1];
        else             v = sh[(i >> 1) - 1] + g_a[i];
        g_b[i] = v;
    }
    __syncthreads();  // makes g_b writes visible within the block

    // derive idx / main / cross — faithful to the reference formula,
    // no monotonicity assumption.
    for (int i = tid; i < N; i += 1024) {
        const float b = g_b[i];
        const float a = g_a[i];
        int idx  = (int)floorf(b);
        int prev = (i == 0) ? 0 : (int)floorf(g_b[i - 1]);
        const bool same = (idx == prev);
        const float frac = b - (float)idx;
        g_m[i] = same ? a : frac;
        g_c[i] = same ? 0.f : (a - frac);
        if (idx < 0) idx = 0;
        if (idx > N - 1) idx = N - 1;
        g_row0[i] = idx;
        int r1 = same ? -1 : (idx - 1);
        if (r1 > N - 1) r1 = -1;
        g_row1[i] = r1;
    }
}

// ---------------------------------------------------------------------------
// Kernel 3: scatter  out[row0_i] += m_i * x_i ;  out[row1_i] += c_i * x_i
// One block per column i, 256 threads x float4 = 1024 floats.
// Vector reductions via red.global.add.v4.f32 (sm_90+).
// ---------------------------------------------------------------------------
__device__ __forceinline__ void red_add_v4(float4* addr, float a, float b,
                                           float c, float d) {
    asm volatile("red.global.add.v4.f32 [%0], {%1,%2,%3,%4};"
                 :: "l"(addr), "f"(a), "f"(b), "f"(c), "f"(d)
                 : "memory");
}

__global__ void k_scatter(const float* __restrict__ x, float* __restrict__ out) {
    const int i = blockIdx.x;     // column
    const int t = threadIdx.x;    // 0..255

    const float m  = g_m[i];
    const float c  = g_c[i];
    const int   r0 = g_row0[i];
    const int   r1 = g_row1[i];

    const float4 v = reinterpret_cast<const float4*>(x)[i * (D / 4) + t];

    float4* o = reinterpret_cast<float4*>(out);
    red_add_v4(&o[r0 * (D / 4) + t], m * v.x, m * v.y, m * v.z, m * v.w);
    if (r1 >= 0) {
        red_add_v4(&o[r1 * (D / 4) + t], c * v.x, c * v.y, c * v.z, c * v.w);
    }
}

// ---------------------------------------------------------------------------
extern "C" void kernel_launch(void* const* d_in, const int* in_sizes, int n_in,
                              void* d_out, int out_size) {
    const float* x = (const float*)d_in[0];   // [8192, 1024] f32
    const float* w = (const float*)d_in[1];   // [1024, 1]    f32
    float* out = (float*)d_out;               // [8192, 1024] f32

    cudaMemsetAsync(out, 0, (size_t)N * D * sizeof(float), 0);
    k_logits<<<N / 8, 256>>>(x, w);
    k_scan<<<1, 1024>>>();
    k_scatter<<<N, 256>>>(x, out);
}